// round 1
// baseline (speedup 1.0000x reference)
#include <cuda_runtime.h>

#define NB        32768
#define SEQ       32
#define HID       64
#define VOC       64
#define SLOTS     8

// Precomputed tables (device globals: no allocation allowed)
__device__ float        g_score[64];       // eviction score per vocab token
__device__ float        g_Q1[64 * 64];     // embed[t] @ rh_w1[0:64]  + rh_b1   (query half of layer1)
__device__ float        g_E1[64 * 64];     // (1/8) * embed[t] @ rh_w1[64:128]  (memory half of layer1)
__device__ unsigned int g_seq8[NB * 8];    // seqs packed to bytes, 4 tokens per u32

// ---------------------------------------------------------------------------
// Precompute: per-token score table + layer1 token tables.
// grid = 64 blocks (token t), 64 threads (output dim o).
// ---------------------------------------------------------------------------
__global__ void precompute_k(const float* __restrict__ emb,
                             const float* __restrict__ sw1,  // (64,32)
                             const float* __restrict__ sb1,  // (32,)
                             const float* __restrict__ sw2,  // (32,1)
                             const float* __restrict__ sb2,  // (1,)
                             const float* __restrict__ w1,   // (128,64)
                             const float* __restrict__ b1)   // (64,)
{
    const int t = blockIdx.x;
    const int o = threadIdx.x;
    __shared__ float s_e[64];
    s_e[o] = emb[t * HID + o];
    __syncthreads();

    // Q1 / E1 rows
    float aq = b1[o];
    float ae = 0.0f;
#pragma unroll 8
    for (int k = 0; k < 64; k++) {
        const float v = s_e[k];
        aq = fmaf(v, w1[k * 64 + o], aq);
        ae = fmaf(v, w1[(64 + k) * 64 + o], ae);
    }
    g_Q1[t * 64 + o] = aq;
    g_E1[t * 64 + o] = ae * 0.125f;

    // Score: score(t) = sum_k relu(emb[t]@sw1 + sb1)[k] * sw2[k]  + sb2
    if (o < 32) {
        float h = sb1[o];
#pragma unroll 8
        for (int d = 0; d < 64; d++) h = fmaf(s_e[d], sw1[d * 32 + o], h);
        float p = fmaxf(h, 0.0f) * sw2[o];
#pragma unroll
        for (int off = 16; off > 0; off >>= 1)
            p += __shfl_down_sync(0xffffffffu, p, off);
        if (o == 0) g_score[t] = p + sb2[0];
    }
}

// ---------------------------------------------------------------------------
// Pack seqs (int32 tokens 0..63) into bytes, 4 per u32.
// ---------------------------------------------------------------------------
__global__ void pack_k(const int* __restrict__ seqs)
{
    const int j = blockIdx.x * blockDim.x + threadIdx.x;
    if (j < NB * 8) {
        const int4 v = ((const int4*)seqs)[j];
        g_seq8[j] = (unsigned)(v.x & 63) | ((unsigned)(v.y & 63) << 8) |
                    ((unsigned)(v.z & 63) << 16) | ((unsigned)(v.w & 63) << 24);
    }
}

// ---------------------------------------------------------------------------
// Main kernel: one thread per batch item.
//   1) token-level eviction scan (scores from shared table)
//   2) layer1 = Q1[q] + sum_s E1[slot_s]      (table adds, no GEMM)
//   3) layer2 = relu(a) @ rh_w2 + rh_b2       (4096 FFMA/thread)
// ---------------------------------------------------------------------------
__global__ void __launch_bounds__(256) main_k(const int*   __restrict__ qtok,
                                              const float* __restrict__ w2,   // (64,64)
                                              const float* __restrict__ b2,   // (64,)
                                              float*       __restrict__ out)
{
    __shared__ float s_sc[64];
    __shared__ float s_E1[64 * 65];   // padded rows: bank = (t + o) % 32
    __shared__ float s_W2[64 * 64];
    __shared__ float s_b2[64];

    const int tid = threadIdx.x;
    if (tid < 64) { s_sc[tid] = g_score[tid]; s_b2[tid] = b2[tid]; }
#pragma unroll 4
    for (int i = tid; i < 4096; i += 256) {
        s_W2[i] = w2[i];
        s_E1[(i >> 6) * 65 + (i & 63)] = g_E1[i];
    }
    __syncthreads();

    const int item = blockIdx.x * 256 + tid;

    // 32 tokens as 8 packed words (2 x 16B coalesced loads)
    const uint4 v0 = *((const uint4*)g_seq8 + item * 2);
    const uint4 v1 = *((const uint4*)g_seq8 + item * 2 + 1);
    unsigned int wv[8] = {v0.x, v0.y, v0.z, v0.w, v1.x, v1.y, v1.z, v1.w};

    // Fill phase: first 8 tokens occupy the 8 slots
    int   tok[SLOTS];
    float sc[SLOTS];
#pragma unroll
    for (int j = 0; j < SLOTS; j++) {
        tok[j] = (int)((wv[j >> 2] >> ((j & 3) * 8)) & 0xFFu);
        sc[j]  = s_sc[tok[j]];
    }

    // Eviction phase: steps 8..30 (scan covers seqs[:, :31])
#pragma unroll
    for (int step = 8; step < 31; step++) {
        const int   nt = (int)((wv[step >> 2] >> ((step & 3) * 8)) & 0xFFu);
        const float ns = s_sc[nt];
        // argmin (first minimum, matching jnp.argmin tie-break)
        float best = sc[0];
        int   bi   = 0;
#pragma unroll
        for (int j = 1; j < SLOTS; j++)
            if (sc[j] < best) { best = sc[j]; bi = j; }
        // remove slot bi, shift later slots down, append new token at slot 7
#pragma unroll
        for (int j = 0; j < SLOTS - 1; j++)
            if (j >= bi) { tok[j] = tok[j + 1]; sc[j] = sc[j + 1]; }
        tok[SLOTS - 1] = nt;
        sc[SLOTS - 1]  = ns;
    }

    int base[SLOTS];
#pragma unroll
    for (int s = 0; s < SLOTS; s++) base[s] = tok[s] * 65;

    // Output accumulators (init with bias b2)
    float acc[64];
#pragma unroll
    for (int o = 0; o < 64; o++) acc[o] = s_b2[o];

    const int q = qtok[item] & 63;
    const float4* __restrict__ Q1v = (const float4*)g_Q1 + q * 16;  // L1-resident 16KB table
    const float4* __restrict__ W2v = (const float4*)s_W2;

    for (int og = 0; og < 16; og++) {          // 4 layer1-outputs per iteration
        const float4 aq = Q1v[og];
        const int    oo = og * 4;
        float a0 = aq.x, a1 = aq.y, a2 = aq.z, a3 = aq.w;
#pragma unroll
        for (int s = 0; s < SLOTS; s++) {
            const int ba = base[s] + oo;
            a0 += s_E1[ba + 0];
            a1 += s_E1[ba + 1];
            a2 += s_E1[ba + 2];
            a3 += s_E1[ba + 3];
        }
        a0 = fmaxf(a0, 0.0f);
        a1 = fmaxf(a1, 0.0f);
        a2 = fmaxf(a2, 0.0f);
        a3 = fmaxf(a3, 0.0f);

        // acc[:] += a0*W2[oo] + a1*W2[oo+1] + a2*W2[oo+2] + a3*W2[oo+3]
        const float4* Wr = W2v + oo * 16;
#pragma unroll
        for (int jg = 0; jg < 16; jg++) {
            const float4 wA = Wr[jg];           // row oo
            const float4 wB = Wr[16 + jg];      // row oo+1
            const float4 wC = Wr[32 + jg];      // row oo+2
            const float4 wD = Wr[48 + jg];      // row oo+3
            acc[4 * jg + 0] = fmaf(a3, wD.x, fmaf(a2, wC.x, fmaf(a1, wB.x, fmaf(a0, wA.x, acc[4 * jg + 0]))));
            acc[4 * jg + 1] = fmaf(a3, wD.y, fmaf(a2, wC.y, fmaf(a1, wB.y, fmaf(a0, wA.y, acc[4 * jg + 1]))));
            acc[4 * jg + 2] = fmaf(a3, wD.z, fmaf(a2, wC.z, fmaf(a1, wB.z, fmaf(a0, wA.z, acc[4 * jg + 2]))));
            acc[4 * jg + 3] = fmaf(a3, wD.w, fmaf(a2, wC.w, fmaf(a1, wB.w, fmaf(a0, wA.w, acc[4 * jg + 3]))));
        }
    }

    // Write out (16 x STG.128)
    float4* ov = (float4*)(out + (size_t)item * 64);
#pragma unroll
    for (int g = 0; g < 16; g++)
        ov[g] = make_float4(acc[4 * g], acc[4 * g + 1], acc[4 * g + 2], acc[4 * g + 3]);
}

// ---------------------------------------------------------------------------
extern "C" void kernel_launch(void* const* d_in, const int* in_sizes, int n_in,
                              void* d_out, int out_size)
{
    const int*   seqs = (const int*)  d_in[0];
    const int*   qtok = (const int*)  d_in[1];
    const float* emb  = (const float*)d_in[2];
    const float* sw1  = (const float*)d_in[3];
    const float* sb1  = (const float*)d_in[4];
    const float* sw2  = (const float*)d_in[5];
    const float* sb2  = (const float*)d_in[6];
    const float* w1   = (const float*)d_in[7];
    const float* b1   = (const float*)d_in[8];
    const float* w2   = (const float*)d_in[9];
    const float* b2   = (const float*)d_in[10];
    float* out = (float*)d_out;

    precompute_k<<<64, 64>>>(emb, sw1, sb1, sw2, sb2, w1, b1);
    pack_k<<<(NB * 8 + 255) / 256, 256>>>(seqs);
    main_k<<<NB / 256, 256>>>(qtok, w2, b2, out);
}

// round 2
// speedup vs baseline: 1.2166x; 1.2166x over previous
#include <cuda_runtime.h>

#define NB        32768
#define SEQ       32
#define HID       64
#define VOC       64
#define SLOTS     8
#define E1STRIDE  66   // pad: bank = (tok + pair) % 32 -> conflict only if dTok % 32 == 0

__device__ float g_score[64];     // eviction score per vocab token
__device__ float g_Q1[64 * 64];   // embed[t] @ rh_w1[0:64] + rh_b1
__device__ float g_E1[64 * 64];   // (1/8) * embed[t] @ rh_w1[64:128]

// packed f32x2 helpers (Blackwell FFMA2 path)
#define FFMA2(acc, w, a) asm("fma.rn.f32x2 %0, %1, %2, %0;" : "+l"(acc) : "l"(w), "l"(a))
#define ADD2(acc, v)     asm("add.rn.f32x2 %0, %0, %1;"     : "+l"(acc) : "l"(v))
#define PACK2(d, lo, hi) asm("mov.b64 %0, {%1, %2};"        : "=l"(d)   : "f"(lo), "f"(hi))
#define UNPACK2(lo, hi, s) asm("mov.b64 {%0, %1}, %2;"      : "=f"(lo), "=f"(hi) : "l"(s))

typedef unsigned long long u64;

// ---------------------------------------------------------------------------
// Fast precompute: grid=64 (token), block=128. emb row staged in shared;
// 64 fully-unrolled independent LDGs per thread (high MLP). Score folded in.
// ---------------------------------------------------------------------------
__global__ void __launch_bounds__(128) precompute_k(
    const float* __restrict__ emb,
    const float* __restrict__ sw1, const float* __restrict__ sb1,
    const float* __restrict__ sw2, const float* __restrict__ sb2,
    const float* __restrict__ w1,  const float* __restrict__ b1)
{
    const int t   = blockIdx.x;
    const int tid = threadIdx.x;
    __shared__ float s_e[64];
    if (tid < 16) ((float4*)s_e)[tid] = ((const float4*)(emb + t * HID))[tid];
    __syncthreads();

    const int half = tid >> 6;      // 0 -> Q1, 1 -> E1
    const int o    = tid & 63;
    const float* wcol = w1 + half * 64 * 64 + o;
    float acc = half ? 0.0f : b1[o];
#pragma unroll
    for (int k = 0; k < 64; k++) acc = fmaf(s_e[k], wcol[k * 64], acc);
    if (half) g_E1[t * 64 + o] = acc * 0.125f;
    else      g_Q1[t * 64 + o] = acc;

    if (tid < 32) {
        float h = sb1[tid];
#pragma unroll
        for (int d = 0; d < 64; d++) h = fmaf(s_e[d], sw1[d * 32 + tid], h);
        float p = fmaxf(h, 0.0f) * sw2[tid];
#pragma unroll
        for (int off = 16; off > 0; off >>= 1)
            p += __shfl_down_sync(0xffffffffu, p, off);
        if (tid == 0) g_score[t] = p + sb2[0];
    }
}

// ---------------------------------------------------------------------------
// Main kernel: 256 blocks x 128 threads, 1 item/thread (2 CTAs/SM resident).
// Direct seqs read (no pack kernel). Layer-2 GEMM with packed f32x2 FMA.
// ---------------------------------------------------------------------------
__global__ void __launch_bounds__(128, 2) main_k(
    const int*   __restrict__ seqs,
    const int*   __restrict__ qtok,
    const float* __restrict__ w2,    // (64,64)
    const float* __restrict__ b2,    // (64,)
    float*       __restrict__ out)
{
    __shared__ float s_sc[64];
    __shared__ float s_E1[64 * E1STRIDE];
    __shared__ float s_W2[64 * 64];
    __shared__ float s_b2[64];

    const int tid = threadIdx.x;
    if (tid < 64) { s_sc[tid] = g_score[tid]; s_b2[tid] = b2[tid]; }
#pragma unroll
    for (int i4 = tid; i4 < 1024; i4 += 128) {         // W2: float4 copy
        ((float4*)s_W2)[i4] = ((const float4*)w2)[i4];
        const float4 e = ((const float4*)g_E1)[i4];    // E1: padded store
        const int row = i4 >> 4, c = (i4 & 15) * 4;
        float* d = s_E1 + row * E1STRIDE + c;
        d[0] = e.x; d[1] = e.y; d[2] = e.z; d[3] = e.w;
    }
    __syncthreads();

    const int item = blockIdx.x * 128 + tid;

    // ---- load 32 tokens directly (8 x LDG.128) ----
    const int4* sp = (const int4*)seqs + item * 8;
    int t32[32];
#pragma unroll
    for (int g = 0; g < 8; g++) {
        const int4 v = sp[g];
        t32[4 * g + 0] = v.x & 63; t32[4 * g + 1] = v.y & 63;
        t32[4 * g + 2] = v.z & 63; t32[4 * g + 3] = v.w & 63;
    }

    // ---- eviction scan (token-level, scores from table) ----
    int   tok[SLOTS];
    float sc [SLOTS];
#pragma unroll
    for (int j = 0; j < SLOTS; j++) { tok[j] = t32[j]; sc[j] = s_sc[tok[j]]; }
#pragma unroll
    for (int step = 8; step < 31; step++) {
        const int   nt = t32[step];
        const float ns = s_sc[nt];
        float best = sc[0]; int bi = 0;
#pragma unroll
        for (int j = 1; j < SLOTS; j++)
            if (sc[j] < best) { best = sc[j]; bi = j; }
#pragma unroll
        for (int j = 0; j < SLOTS - 1; j++)
            if (j >= bi) { tok[j] = tok[j + 1]; sc[j] = sc[j + 1]; }
        tok[SLOTS - 1] = nt; sc[SLOTS - 1] = ns;
    }
    int base[SLOTS];
#pragma unroll
    for (int s = 0; s < SLOTS; s++) base[s] = tok[s] * E1STRIDE;

    // ---- output accumulators as 32 packed f32x2 pairs (init = b2) ----
    u64 accp[32];
#pragma unroll
    for (int p = 0; p < 32; p++) accp[p] = ((const u64*)s_b2)[p];

    const int q = qtok[item] & 63;
    const float4* __restrict__ Q1v = (const float4*)g_Q1 + q * 16;  // L1-hot
    const ulonglong2* __restrict__ Wq = (const ulonglong2*)s_W2;

#pragma unroll
    for (int og = 0; og < 16; og++) {
        const int oo = og * 4;
        // layer1: Q1 row + 8 slot rows of E1 (packed adds)
        const float4 aq = Q1v[og];
        u64 P0, P1;
        PACK2(P0, aq.x, aq.y);
        PACK2(P1, aq.z, aq.w);
#pragma unroll
        for (int s = 0; s < SLOTS; s++) {
            const u64* e = (const u64*)(s_E1 + base[s] + oo);
            ADD2(P0, e[0]);
            ADD2(P1, e[1]);
        }
        float a0, a1, a2, a3;
        UNPACK2(a0, a1, P0);
        UNPACK2(a2, a3, P1);
        a0 = fmaxf(a0, 0.0f); a1 = fmaxf(a1, 0.0f);
        a2 = fmaxf(a2, 0.0f); a3 = fmaxf(a3, 0.0f);
        u64 A0, A1, A2, A3;
        PACK2(A0, a0, a0); PACK2(A1, a1, a1);
        PACK2(A2, a2, a2); PACK2(A3, a3, a3);

        // acc += a0*W2[oo] + a1*W2[oo+1] + a2*W2[oo+2] + a3*W2[oo+3]
        const ulonglong2* R0 = Wq + (oo + 0) * 16;
        const ulonglong2* R1 = Wq + (oo + 1) * 16;
        const ulonglong2* R2 = Wq + (oo + 2) * 16;
        const ulonglong2* R3 = Wq + (oo + 3) * 16;
#pragma unroll
        for (int jg = 0; jg < 16; jg++) {
            const ulonglong2 w0 = R0[jg];   // LDS.128 broadcast (N=1)
            const ulonglong2 w1v = R1[jg];
            const ulonglong2 w2v = R2[jg];
            const ulonglong2 w3v = R3[jg];
            FFMA2(accp[2 * jg],     w0.x,  A0);
            FFMA2(accp[2 * jg + 1], w0.y,  A0);
            FFMA2(accp[2 * jg],     w1v.x, A1);
            FFMA2(accp[2 * jg + 1], w1v.y, A1);
            FFMA2(accp[2 * jg],     w2v.x, A2);
            FFMA2(accp[2 * jg + 1], w2v.y, A2);
            FFMA2(accp[2 * jg],     w3v.x, A3);
            FFMA2(accp[2 * jg + 1], w3v.y, A3);
        }
    }

    // ---- write out (16 x STG.128) ----
    ulonglong2* ov = (ulonglong2*)(out + (size_t)item * 64);
#pragma unroll
    for (int g = 0; g < 16; g++) {
        ulonglong2 v; v.x = accp[2 * g]; v.y = accp[2 * g + 1];
        ov[g] = v;
    }
}

// ---------------------------------------------------------------------------
extern "C" void kernel_launch(void* const* d_in, const int* in_sizes, int n_in,
                              void* d_out, int out_size)
{
    const int*   seqs = (const int*)  d_in[0];
    const int*   qtok = (const int*)  d_in[1];
    const float* emb  = (const float*)d_in[2];
    const float* sw1  = (const float*)d_in[3];
    const float* sb1  = (const float*)d_in[4];
    const float* sw2  = (const float*)d_in[5];
    const float* sb2  = (const float*)d_in[6];
    const float* w1   = (const float*)d_in[7];
    const float* b1   = (const float*)d_in[8];
    const float* w2   = (const float*)d_in[9];
    const float* b2   = (const float*)d_in[10];
    float* out = (float*)d_out;

    precompute_k<<<64, 128>>>(emb, sw1, sb1, sw2, sb2, w1, b1);
    main_k<<<NB / 128, 128>>>(seqs, qtok, w2, b2, out);
}

// round 4
// speedup vs baseline: 1.3269x; 1.0907x over previous
#include <cuda_runtime.h>

#define NB        32768
#define SLOTS     8
#define E1STRIDE  68      // floats per row (16B-aligned)
#define ASTRIDE   68      // a_sh row stride in floats
#define WBLK      258     // u64 per to-block (32 kp * 8 + 2 pad)

__device__ float g_score[64];
__device__ float g_Q1[64 * 64];   // embed[t] @ rh_w1[0:64] + rh_b1
__device__ float g_E1[64 * 64];   // (1/8) * embed[t] @ rh_w1[64:128]

typedef unsigned long long u64;
typedef unsigned int u32;

#define FFMA2(acc, x, y)  asm("fma.rn.f32x2 %0, %1, %2, %0;" : "+l"(acc) : "l"(x), "l"(y))
#define PACK2(d, lo, hi)  asm("mov.b64 %0, {%1, %2};" : "=l"(d) : "f"(lo), "f"(hi))
#define UNPACK2(lo, hi, s) asm("mov.b64 {%0, %1}, %2;" : "=f"(lo), "=f"(hi) : "l"(s))

// Dynamic smem layout (bytes)
#define OFF_E1   0
#define OFF_A    17408                       // 64*68*4
#define OFF_W    (OFF_A + 34816)             // 128*68*4
#define OFF_SC   (OFF_W + 16512)             // 8*258*8
#define OFF_B2   (OFF_SC + 256)
#define SMEM_TOTAL (OFF_B2 + 256)

// ---------------------------------------------------------------------------
__global__ void __launch_bounds__(128) precompute_k(
    const float* __restrict__ emb,
    const float* __restrict__ sw1, const float* __restrict__ sb1,
    const float* __restrict__ sw2, const float* __restrict__ sb2,
    const float* __restrict__ w1,  const float* __restrict__ b1)
{
    const int t   = blockIdx.x;
    const int tid = threadIdx.x;
    __shared__ float s_e[64];
    if (tid < 16) ((float4*)s_e)[tid] = ((const float4*)(emb + t * 64))[tid];
    __syncthreads();

    const int half = tid >> 6;
    const int o    = tid & 63;
    const float* wcol = w1 + half * 64 * 64 + o;
    float acc = half ? 0.0f : b1[o];
#pragma unroll
    for (int k = 0; k < 64; k++) acc = fmaf(s_e[k], wcol[k * 64], acc);
    if (half) g_E1[t * 64 + o] = acc * 0.125f;
    else      g_Q1[t * 64 + o] = acc;

    if (tid < 32) {
        float h = sb1[tid];
#pragma unroll
        for (int d = 0; d < 64; d++) h = fmaf(s_e[d], sw1[d * 32 + tid], h);
        float p = fmaxf(h, 0.0f) * sw2[tid];
#pragma unroll
        for (int off = 16; off > 0; off >>= 1)
            p += __shfl_down_sync(0xffffffffu, p, off);
        if (tid == 0) g_score[t] = p + sb2[0];
    }
}

// ---------------------------------------------------------------------------
// main_k: 256 CTAs x 128 threads.
// Phase 1: per-thread scan + layer1 -> relu rows into a_sh.
// Phase 2: tiled GEMM, 8 items x 8 outs per thread, f32x2 over k-pairs.
// ---------------------------------------------------------------------------
__global__ void __launch_bounds__(128) main_k(
    const int*   __restrict__ seqs,
    const int*   __restrict__ qtok,
    const float* __restrict__ w2,    // (64 j, 64 o)
    const float* __restrict__ b2,
    float*       __restrict__ out)
{
    extern __shared__ __align__(16) char dyn[];
    float* s_E1 = (float*)(dyn + OFF_E1);
    float* a_sh = (float*)(dyn + OFF_A);
    u64*   w_s  = (u64*)  (dyn + OFF_W);
    float* s_sc = (float*)(dyn + OFF_SC);
    float* s_b2 = (float*)(dyn + OFF_B2);

    const int tid = threadIdx.x;

    // ---- stage tables ----
    if (tid < 64) { s_sc[tid] = g_score[tid]; s_b2[tid] = b2[tid]; }
#pragma unroll
    for (int i4 = tid; i4 < 1024; i4 += 128) {
        const float4 e = ((const float4*)g_E1)[i4];
        *(float4*)(s_E1 + (i4 >> 4) * E1STRIDE + (i4 & 15) * 4) = e;
    }
    // W2 -> per-to blocks of k-pair-packed u64: w_s[to*WBLK + kp*8 + j] = (w[2kp][o], w[2kp+1][o]), o = to*8+j
#pragma unroll
    for (int e = tid; e < 2048; e += 128) {
        const int to = e >> 8, rem = e & 255, kp = rem >> 3, j = rem & 7;
        const int o  = to * 8 + j;
        u64 v;
        PACK2(v, w2[kp * 128 + o], w2[kp * 128 + 64 + o]);
        w_s[to * WBLK + kp * 8 + j] = v;
    }
    __syncthreads();

    // =================== Phase 1: scan + layer1 ===================
    {
        const int item = blockIdx.x * 128 + tid;
        const int4* sp = (const int4*)seqs + item * 8;
        int t32[32];
#pragma unroll
        for (int g = 0; g < 8; g++) {
            const int4 v = sp[g];
            t32[4 * g + 0] = v.x & 63; t32[4 * g + 1] = v.y & 63;
            t32[4 * g + 2] = v.z & 63; t32[4 * g + 3] = v.w & 63;
        }
        int   tok[SLOTS];
        float sc [SLOTS];
#pragma unroll
        for (int j = 0; j < SLOTS; j++) { tok[j] = t32[j]; sc[j] = s_sc[tok[j]]; }
#pragma unroll
        for (int step = 8; step < 31; step++) {
            const int   nt = t32[step];
            const float ns = s_sc[nt];
            float best = sc[0]; int bi = 0;
#pragma unroll
            for (int j = 1; j < SLOTS; j++)
                if (sc[j] < best) { best = sc[j]; bi = j; }
#pragma unroll
            for (int j = 0; j < SLOTS - 1; j++)
                if (j >= bi) { tok[j] = tok[j + 1]; sc[j] = sc[j + 1]; }
            tok[SLOTS - 1] = nt; sc[SLOTS - 1] = ns;
        }

        float a[64];
        const float4* Q1v = (const float4*)g_Q1 + (qtok[item] & 63) * 16;
#pragma unroll
        for (int g = 0; g < 16; g++) {
            const float4 v = Q1v[g];
            a[4 * g] = v.x; a[4 * g + 1] = v.y; a[4 * g + 2] = v.z; a[4 * g + 3] = v.w;
        }
#pragma unroll
        for (int s = 0; s < SLOTS; s++) {
            const float4* e = (const float4*)(s_E1 + tok[s] * E1STRIDE);
#pragma unroll
            for (int g = 0; g < 16; g++) {
                const float4 v = e[g];
                a[4 * g] += v.x; a[4 * g + 1] += v.y; a[4 * g + 2] += v.z; a[4 * g + 3] += v.w;
            }
        }
        float* ar = a_sh + tid * ASTRIDE;
#pragma unroll
        for (int g = 0; g < 16; g++) {
            float4 v;
            v.x = fmaxf(a[4 * g + 0], 0.0f);
            v.y = fmaxf(a[4 * g + 1], 0.0f);
            v.z = fmaxf(a[4 * g + 2], 0.0f);
            v.w = fmaxf(a[4 * g + 3], 0.0f);
            *(float4*)(ar + 4 * g) = v;
        }
    }
    __syncthreads();

    // =================== Phase 2: tiled GEMM ===================
    // thread (ti, to): items {ti + 16*i}, outputs {to*8 + j}
    const int ti = tid & 15;
    const int to = tid >> 4;

    u64 acc[64];
#pragma unroll
    for (int i = 0; i < 64; i++) acc[i] = 0ull;

    const u64* wblk = w_s + to * WBLK;

#pragma unroll
    for (int kk = 0; kk < 16; kk++) {          // 4 k-values (2 k-pairs) per iter
        // A: 8 items, each LDS.128 = k-pairs (kk*4, kk*4+1) and (kk*4+2, kk*4+3)
        u64 A0[8], A1[8];
#pragma unroll
        for (int i = 0; i < 8; i++) {
            const float4 av = *(const float4*)(a_sh + (ti + 16 * i) * ASTRIDE + kk * 4);
            PACK2(A0[i], av.x, av.y);
            PACK2(A1[i], av.z, av.w);
        }
        // W: 2 k-pairs x 8 outputs
        u64 W0[8], W1[8];
        const ulonglong2* w0 = (const ulonglong2*)(wblk + (2 * kk) * 8);
        const ulonglong2* w1 = (const ulonglong2*)(wblk + (2 * kk + 1) * 8);
#pragma unroll
        for (int c = 0; c < 4; c++) {
            const ulonglong2 t0 = w0[c]; W0[2 * c] = t0.x; W0[2 * c + 1] = t0.y;
            const ulonglong2 t1 = w1[c]; W1[2 * c] = t1.x; W1[2 * c + 1] = t1.y;
        }
#pragma unroll
        for (int i = 0; i < 8; i++)
#pragma unroll
            for (int j = 0; j < 8; j++) {
                FFMA2(acc[i * 8 + j], A0[i], W0[j]);
                FFMA2(acc[i * 8 + j], A1[i], W1[j]);
            }
    }

    // epilogue: out = lo + hi + b2
    float bb[8];
#pragma unroll
    for (int j = 0; j < 8; j++) bb[j] = s_b2[to * 8 + j];

#pragma unroll
    for (int i = 0; i < 8; i++) {
        float r[8];
#pragma unroll
        for (int j = 0; j < 8; j++) {
            float lo, hi;
            UNPACK2(lo, hi, acc[i * 8 + j]);
            r[j] = lo + hi + bb[j];
        }
        float* orow = out + (size_t)(blockIdx.x * 128 + ti + 16 * i) * 64 + to * 8;
        *(float4*)(orow)     = make_float4(r[0], r[1], r[2], r[3]);
        *(float4*)(orow + 4) = make_float4(r[4], r[5], r[6], r[7]);
    }
}

// ---------------------------------------------------------------------------
extern "C" void kernel_launch(void* const* d_in, const int* in_sizes, int n_in,
                              void* d_out, int out_size)
{
    const int*   seqs = (const int*)  d_in[0];
    const int*   qtok = (const int*)  d_in[1];
    const float* emb  = (const float*)d_in[2];
    const float* sw1  = (const float*)d_in[3];
    const float* sb1  = (const float*)d_in[4];
    const float* sw2  = (const float*)d_in[5];
    const float* sb2  = (const float*)d_in[6];
    const float* w1   = (const float*)d_in[7];
    const float* b1   = (const float*)d_in[8];
    const float* w2   = (const float*)d_in[9];
    const float* b2   = (const float*)d_in[10];
    float* out = (float*)d_out;

    cudaFuncSetAttribute(main_k, cudaFuncAttributeMaxDynamicSharedMemorySize, SMEM_TOTAL);

    precompute_k<<<64, 128>>>(emb, sw1, sb1, sw2, sb2, w1, b1);
    main_k<<<NB / 128, 128, SMEM_TOTAL>>>(seqs, qtok, w2, b2, out);
}

// round 5
// speedup vs baseline: 1.4451x; 1.0890x over previous
#include <cuda_runtime.h>

#define NB      32768
#define SLOTS   8
#define WBLK    258   // u64 per to-block: 32 kp * 8 + 2 pad (bank-clean, verified)

__device__ float g_score[64];
__device__ float g_Q1[64 * 64];   // embed[t] @ rh_w1[0:64] + rh_b1
__device__ float g_E1[64 * 64];   // (1/8) * embed[t] @ rh_w1[64:128]

typedef unsigned long long u64;
typedef unsigned int u32;

#define FFMA2(acc, x, y)   asm("fma.rn.f32x2 %0, %1, %2, %0;" : "+l"(acc) : "l"(x), "l"(y))
#define ADD2(acc, v)       asm("add.rn.f32x2 %0, %0, %1;"     : "+l"(acc) : "l"(v))
#define PACK2(d, lo, hi)   asm("mov.b64 %0, {%1, %2};" : "=l"(d) : "f"(lo), "f"(hi))
#define UNPACK2(lo, hi, s) asm("mov.b64 {%0, %1}, %2;" : "=f"(lo), "=f"(hi) : "l"(s))

// Dynamic smem layout (bytes)
#define OFF_E1   0                       // float[64*68]   = 17408
#define OFF_A    17408                   // float4[16*128] = 32768  ([kk][item], XOR swizzled)
#define OFF_W    50176                   // u64[8*258]     = 16512
#define OFF_SC   66688                   // float[64]
#define OFF_B2   66944                   // float[64]
#define OFF_TOK  67200                   // u64[128]
#define OFF_Q    68224                   // int[128]
#define SMEM_TOTAL 68736

// ---------------------------------------------------------------------------
__global__ void __launch_bounds__(128) precompute_k(
    const float* __restrict__ emb,
    const float* __restrict__ sw1, const float* __restrict__ sb1,
    const float* __restrict__ sw2, const float* __restrict__ sb2,
    const float* __restrict__ w1,  const float* __restrict__ b1)
{
    const int t   = blockIdx.x;
    const int tid = threadIdx.x;
    __shared__ float s_e[64];
    if (tid < 16) ((float4*)s_e)[tid] = ((const float4*)(emb + t * 64))[tid];
    __syncthreads();

    const int half = tid >> 6;
    const int o    = tid & 63;
    const float* wcol = w1 + half * 64 * 64 + o;
    float acc = half ? 0.0f : b1[o];
#pragma unroll
    for (int k = 0; k < 64; k++) acc = fmaf(s_e[k], wcol[k * 64], acc);
    if (half) g_E1[t * 64 + o] = acc * 0.125f;
    else      g_Q1[t * 64 + o] = acc;

    if (tid < 32) {
        float h = sb1[tid];
#pragma unroll
        for (int d = 0; d < 64; d++) h = fmaf(s_e[d], sw1[d * 32 + tid], h);
        float p = fmaxf(h, 0.0f) * sw2[tid];
#pragma unroll
        for (int off = 16; off > 0; off >>= 1)
            p += __shfl_down_sync(0xffffffffu, p, off);
        if (tid == 0) g_score[t] = p + sb2[0];
    }
}

// ---------------------------------------------------------------------------
// main_k: 256 CTAs x 128 threads, 3 CTAs/SM target.
//  1a: per-thread scan -> packed tokens to smem
//  1b: warp-cooperative conflict-free gather -> swizzled A[kk][item] in smem
//  2 : register-tiled GEMM (4 items x 8 outs, two halves), f32x2 FMA
// ---------------------------------------------------------------------------
__global__ void __launch_bounds__(128, 3) main_k(
    const int*   __restrict__ seqs,
    const int*   __restrict__ qtok,
    const float* __restrict__ w2,    // (64 k, 64 o)
    const float* __restrict__ b2,
    float*       __restrict__ out)
{
    extern __shared__ __align__(16) char dyn[];
    float*      s_E1  = (float*)(dyn + OFF_E1);
    float4*     s_A4  = (float4*)(dyn + OFF_A);
    u64*        s_W   = (u64*)(dyn + OFF_W);
    float*      s_sc  = (float*)(dyn + OFF_SC);
    float*      s_b2  = (float*)(dyn + OFF_B2);
    u64*        s_tok = (u64*)(dyn + OFF_TOK);
    int*        s_q   = (int*)(dyn + OFF_Q);

    const int tid = threadIdx.x;

    // ---- stage tables ----
    if (tid < 64) { s_sc[tid] = g_score[tid]; s_b2[tid] = b2[tid]; }
#pragma unroll
    for (int i4 = tid; i4 < 1024; i4 += 128) {
        const float4 e = ((const float4*)g_E1)[i4];
        *(float4*)(s_E1 + (i4 >> 4) * 68 + (i4 & 15) * 4) = e;
    }
#pragma unroll
    for (int e = tid; e < 2048; e += 128) {
        const int to = e >> 8, rem = e & 255, kp = rem >> 3, j = rem & 7;
        const int o  = to * 8 + j;
        u64 v;
        PACK2(v, w2[kp * 128 + o], w2[kp * 128 + 64 + o]);
        s_W[to * WBLK + kp * 8 + j] = v;
    }
    __syncthreads();

    // =============== phase 1a: per-thread eviction scan ===============
    {
        const int item = blockIdx.x * 128 + tid;
        const int4* sp = (const int4*)seqs + item * 8;
        int t32[32];
#pragma unroll
        for (int g = 0; g < 8; g++) {
            const int4 v = sp[g];
            t32[4 * g + 0] = v.x & 63; t32[4 * g + 1] = v.y & 63;
            t32[4 * g + 2] = v.z & 63; t32[4 * g + 3] = v.w & 63;
        }
        int   tok[SLOTS];
        float sc [SLOTS];
#pragma unroll
        for (int j = 0; j < SLOTS; j++) { tok[j] = t32[j]; sc[j] = s_sc[tok[j]]; }
#pragma unroll
        for (int step = 8; step < 31; step++) {
            const int   nt = t32[step];
            const float ns = s_sc[nt];
            float best = sc[0]; int bi = 0;
#pragma unroll
            for (int j = 1; j < SLOTS; j++)
                if (sc[j] < best) { best = sc[j]; bi = j; }
#pragma unroll
            for (int j = 0; j < SLOTS - 1; j++)
                if (j >= bi) { tok[j] = tok[j + 1]; sc[j] = sc[j + 1]; }
            tok[SLOTS - 1] = nt; sc[SLOTS - 1] = ns;
        }
        u64 t8 = 0;
#pragma unroll
        for (int s = 0; s < SLOTS; s++) t8 |= (u64)(u32)tok[s] << (8 * s);
        s_tok[tid] = t8;
        s_q[tid]   = qtok[item] & 63;
    }
    __syncthreads();

    // =============== phase 1b: cooperative gather (conflict-free) ===============
    {
        const int lane = tid & 31;
        const int wrp  = tid >> 5;
        const int o4   = lane & 15;       // float4 index within row == kk
        const int hi16 = lane >> 4;       // which of 2 items this half-warp handles
        const ulonglong2* E1q = (const ulonglong2*)s_E1;
        const ulonglong2* Q1q = (const ulonglong2*)g_Q1;
        ulonglong2* A2 = (ulonglong2*)s_A4;
#pragma unroll 4
        for (int p = 0; p < 16; p++) {
            const int it = wrp * 32 + 2 * p + hi16;
            const u64 t8 = s_tok[it];
            const int q  = s_q[it];
            const ulonglong2 qv = Q1q[q * 16 + o4];   // L1-hot LDG.128, coalesced
            u64 P0 = qv.x, P1 = qv.y;
#pragma unroll
            for (int s = 0; s < SLOTS; s++) {
                const int tk = (int)((t8 >> (8 * s)) & 63);
                const ulonglong2 ev = E1q[tk * 17 + o4];  // contiguous per half-warp
                ADD2(P0, ev.x);
                ADD2(P1, ev.y);
            }
            float f0, f1, f2, f3;
            UNPACK2(f0, f1, P0); UNPACK2(f2, f3, P1);
            f0 = fmaxf(f0, 0.0f); f1 = fmaxf(f1, 0.0f);
            f2 = fmaxf(f2, 0.0f); f3 = fmaxf(f3, 0.0f);
            ulonglong2 st;
            PACK2(st.x, f0, f1); PACK2(st.y, f2, f3);
            A2[o4 * 128 + (it ^ (o4 & 7))] = st;      // swizzled, conflict-free
        }
    }
    __syncthreads();

    // =============== phase 2: register-tiled GEMM ===============
    const int to = tid & 7;               // output group (8 outs)
    const int ti = tid >> 3;              // item lane (0..15)
    float bb[8];
#pragma unroll
    for (int j = 0; j < 8; j++) bb[j] = s_b2[to * 8 + j];

    const ulonglong2* A2 = (const ulonglong2*)s_A4;
    const u64* wblk = s_W + to * WBLK;

#pragma unroll
    for (int h = 0; h < 2; h++) {
        u64 acc[32];
#pragma unroll
        for (int i = 0; i < 32; i++) acc[i] = 0ull;

#pragma unroll 4
        for (int kk = 0; kk < 16; kk++) {
            const int z = kk & 7;
            u64 A0[4], A1[4];
#pragma unroll
            for (int i2 = 0; i2 < 4; i2++) {
                const int it = ti + 16 * (4 * h + i2);
                const ulonglong2 av = A2[kk * 128 + (it ^ z)];   // broadcast read
                A0[i2] = av.x; A1[i2] = av.y;
            }
            u64 W0[8], W1[8];
            const ulonglong2* wp0 = (const ulonglong2*)(wblk + (2 * kk) * 8);
            const ulonglong2* wp1 = (const ulonglong2*)(wblk + (2 * kk + 1) * 8);
#pragma unroll
            for (int c = 0; c < 4; c++) {
                const ulonglong2 a = wp0[c]; W0[2 * c] = a.x; W0[2 * c + 1] = a.y;
                const ulonglong2 b = wp1[c]; W1[2 * c] = b.x; W1[2 * c + 1] = b.y;
            }
#pragma unroll
            for (int i2 = 0; i2 < 4; i2++)
#pragma unroll
                for (int j = 0; j < 8; j++) {
                    FFMA2(acc[i2 * 8 + j], A0[i2], W0[j]);
                    FFMA2(acc[i2 * 8 + j], A1[i2], W1[j]);
                }
        }

        // epilogue (coalesced per-warp: contiguous item rows)
#pragma unroll
        for (int i2 = 0; i2 < 4; i2++) {
            float r[8];
#pragma unroll
            for (int j = 0; j < 8; j++) {
                float lo, hifl;
                UNPACK2(lo, hifl, acc[i2 * 8 + j]);
                r[j] = lo + hifl + bb[j];
            }
            const int item = blockIdx.x * 128 + ti + 16 * (4 * h + i2);
            float* orow = out + (size_t)item * 64 + to * 8;
            *(float4*)(orow)     = make_float4(r[0], r[1], r[2], r[3]);
            *(float4*)(orow + 4) = make_float4(r[4], r[5], r[6], r[7]);
        }
    }
}

// ---------------------------------------------------------------------------
extern "C" void kernel_launch(void* const* d_in, const int* in_sizes, int n_in,
                              void* d_out, int out_size)
{
    const int*   seqs = (const int*)  d_in[0];
    const int*   qtok = (const int*)  d_in[1];
    const float* emb  = (const float*)d_in[2];
    const float* sw1  = (const float*)d_in[3];
    const float* sb1  = (const float*)d_in[4];
    const float* sw2  = (const float*)d_in[5];
    const float* sb2  = (const float*)d_in[6];
    const float* w1   = (const float*)d_in[7];
    const float* b1   = (const float*)d_in[8];
    const float* w2   = (const float*)d_in[9];
    const float* b2   = (const float*)d_in[10];
    float* out = (float*)d_out;

    cudaFuncSetAttribute(main_k, cudaFuncAttributeMaxDynamicSharedMemorySize, SMEM_TOTAL);

    precompute_k<<<64, 128>>>(emb, sw1, sb1, sw2, sb2, w1, b1);
    main_k<<<NB / 128, 128, SMEM_TOTAL>>>(seqs, qtok, w2, b2, out);
}

// round 6
// speedup vs baseline: 1.5863x; 1.0977x over previous
#include <cuda_runtime.h>

#define NB      32768
#define SLOTS   8
#define WBLK    258   // u64 per to-block: 32 kp * 8 + 2 pad

__device__ float g_score[64];
__device__ float g_Q1[64 * 64];   // embed[t] @ rh_w1[0:64] + rh_b1
__device__ float g_E1[64 * 64];   // (1/8) * embed[t] @ rh_w1[64:128]

typedef unsigned long long u64;
typedef unsigned int u32;

#define FFMA2(acc, x, y)   asm("fma.rn.f32x2 %0, %1, %2, %0;" : "+l"(acc) : "l"(x), "l"(y))
#define ADD2(acc, v)       asm("add.rn.f32x2 %0, %0, %1;"     : "+l"(acc) : "l"(v))
#define PACK2(d, lo, hi)   asm("mov.b64 %0, {%1, %2};" : "=l"(d) : "f"(lo), "f"(hi))
#define UNPACK2(lo, hi, s) asm("mov.b64 {%0, %1}, %2;" : "=f"(lo), "=f"(hi) : "l"(s))

// Dynamic smem layout (bytes)
#define OFF_E1   0                       // float[64*68]   = 17408
#define OFF_A    17408                   // float4[16*128] = 32768  ([kk][item], XOR swizzled)
#define OFF_W    50176                   // u64[8*258]     = 16512
#define OFF_SC   66688                   // float[64]
#define OFF_B2   66944                   // float[64]
#define OFF_TOK  67200                   // u64[128]
#define OFF_Q    68224                   // int[128]
#define SMEM_TOTAL 68736

// ---------------------------------------------------------------------------
__global__ void __launch_bounds__(128) precompute_k(
    const float* __restrict__ emb,
    const float* __restrict__ sw1, const float* __restrict__ sb1,
    const float* __restrict__ sw2, const float* __restrict__ sb2,
    const float* __restrict__ w1,  const float* __restrict__ b1)
{
    const int t   = blockIdx.x;
    const int tid = threadIdx.x;
    __shared__ float s_e[64];
    if (tid < 16) ((float4*)s_e)[tid] = ((const float4*)(emb + t * 64))[tid];
    __syncthreads();

    const int half = tid >> 6;
    const int o    = tid & 63;
    const float* wcol = w1 + half * 64 * 64 + o;
    float acc = half ? 0.0f : b1[o];
#pragma unroll
    for (int k = 0; k < 64; k++) acc = fmaf(s_e[k], wcol[k * 64], acc);
    if (half) g_E1[t * 64 + o] = acc * 0.125f;
    else      g_Q1[t * 64 + o] = acc;

    if (tid < 32) {
        float h = sb1[tid];
#pragma unroll
        for (int d = 0; d < 64; d++) h = fmaf(s_e[d], sw1[d * 32 + tid], h);
        float p = fmaxf(h, 0.0f) * sw2[tid];
#pragma unroll
        for (int off = 16; off > 0; off >>= 1)
            p += __shfl_down_sync(0xffffffffu, p, off);
        if (tid == 0) g_score[t] = p + sb2[0];
    }
}

// ---------------------------------------------------------------------------
// main_k: 256 CTAs x 256 threads (2 CTAs/SM -> 16 warps/SM), 128 items/CTA.
//  1a: warps 0-3 scan (1 item/thread) WHILE warps 4-7 stage E1/W2
//  1b: all 8 warps: conflict-free gather -> swizzled A[kk][item]
//  2 : register-tiled GEMM: 4 items x 8 outs per thread, f32x2 FMA
// ---------------------------------------------------------------------------
__global__ void __launch_bounds__(256, 2) main_k(
    const int*   __restrict__ seqs,
    const int*   __restrict__ qtok,
    const float* __restrict__ w2,    // (64 k, 64 o)
    const float* __restrict__ b2,
    float*       __restrict__ out)
{
    extern __shared__ __align__(16) char dyn[];
    float*  s_E1  = (float*)(dyn + OFF_E1);
    float4* s_A4  = (float4*)(dyn + OFF_A);
    u64*    s_W   = (u64*)(dyn + OFF_W);
    float*  s_sc  = (float*)(dyn + OFF_SC);
    float*  s_b2  = (float*)(dyn + OFF_B2);
    u64*    s_tok = (u64*)(dyn + OFF_TOK);
    int*    s_q   = (int*)(dyn + OFF_Q);

    const int tid = threadIdx.x;

    // ---- stage score table + bias first (needed by scan warps) ----
    if (tid >= 128 && tid < 192) {
        const int i = tid - 128;
        s_sc[i] = g_score[i];
        s_b2[i] = b2[i];
    }
    __syncthreads();

    if (tid < 128) {
        // =============== warps 0-3: eviction scan ===============
        const int item = blockIdx.x * 128 + tid;
        const int4* sp = (const int4*)seqs + item * 8;
        int t32[32];
#pragma unroll
        for (int g = 0; g < 8; g++) {
            const int4 v = sp[g];
            t32[4 * g + 0] = v.x & 63; t32[4 * g + 1] = v.y & 63;
            t32[4 * g + 2] = v.z & 63; t32[4 * g + 3] = v.w & 63;
        }
        // preload ALL 31 scores (independent LDS, issued before loop)
        float s31[31];
#pragma unroll
        for (int j = 0; j < 31; j++) s31[j] = s_sc[t32[j]];

        int   tok[SLOTS];
        float sc [SLOTS];
#pragma unroll
        for (int j = 0; j < SLOTS; j++) { tok[j] = t32[j]; sc[j] = s31[j]; }
#pragma unroll
        for (int step = 8; step < 31; step++) {
            const int   nt = t32[step];
            const float ns = s31[step];
            float best = sc[0]; int bi = 0;
#pragma unroll
            for (int j = 1; j < SLOTS; j++)
                if (sc[j] < best) { best = sc[j]; bi = j; }
#pragma unroll
            for (int j = 0; j < SLOTS - 1; j++)
                if (j >= bi) { tok[j] = tok[j + 1]; sc[j] = sc[j + 1]; }
            tok[SLOTS - 1] = nt; sc[SLOTS - 1] = ns;
        }
        u64 t8 = 0;
#pragma unroll
        for (int s = 0; s < SLOTS; s++) t8 |= (u64)(u32)tok[s] << (8 * s);
        s_tok[tid] = t8;
        s_q[tid]   = qtok[item] & 63;
    } else {
        // =============== warps 4-7: stage E1 + W2 (overlapped) ===============
        const int t2 = tid - 128;
#pragma unroll
        for (int i4 = t2; i4 < 1024; i4 += 128) {
            const float4 e = ((const float4*)g_E1)[i4];
            *(float4*)(s_E1 + (i4 >> 4) * 68 + (i4 & 15) * 4) = e;
        }
#pragma unroll
        for (int e = t2; e < 2048; e += 128) {
            const int to = e >> 8, rem = e & 255, kp = rem >> 3, j = rem & 7;
            const int o  = to * 8 + j;
            u64 v;
            PACK2(v, w2[kp * 128 + o], w2[kp * 128 + 64 + o]);
            s_W[to * WBLK + kp * 8 + j] = v;
        }
    }
    __syncthreads();

    // =============== phase 1b: cooperative gather (all 8 warps) ===============
    {
        const int lane = tid & 31;
        const int wrp  = tid >> 5;
        const int o4   = lane & 15;       // float4 index within row == kk
        const int hi16 = lane >> 4;
        const ulonglong2* E1q = (const ulonglong2*)s_E1;
        const ulonglong2* Q1q = (const ulonglong2*)g_Q1;
        ulonglong2* A2 = (ulonglong2*)s_A4;
#pragma unroll
        for (int p = 0; p < 8; p++) {
            const int it = wrp * 16 + 2 * p + hi16;
            const u64 t8 = s_tok[it];
            const int q  = s_q[it];
            const ulonglong2 qv = Q1q[q * 16 + o4];
            u64 P0 = qv.x, P1 = qv.y;
#pragma unroll
            for (int s = 0; s < SLOTS; s++) {
                const int tk = (int)((t8 >> (8 * s)) & 63);
                const ulonglong2 ev = E1q[tk * 17 + o4];
                ADD2(P0, ev.x);
                ADD2(P1, ev.y);
            }
            float f0, f1, f2, f3;
            UNPACK2(f0, f1, P0); UNPACK2(f2, f3, P1);
            f0 = fmaxf(f0, 0.0f); f1 = fmaxf(f1, 0.0f);
            f2 = fmaxf(f2, 0.0f); f3 = fmaxf(f3, 0.0f);
            ulonglong2 st;
            PACK2(st.x, f0, f1); PACK2(st.y, f2, f3);
            A2[o4 * 128 + (it ^ (o4 & 7))] = st;
        }
    }
    __syncthreads();

    // =============== phase 2: register-tiled GEMM ===============
    // thread (ti = tid>>3 in 0..31, to = tid&7): items {ti + 32*i2}, outs {to*8+j}
    const int to = tid & 7;
    const int ti = tid >> 3;
    float bb[8];
#pragma unroll
    for (int j = 0; j < 8; j++) bb[j] = s_b2[to * 8 + j];

    const ulonglong2* A2 = (const ulonglong2*)s_A4;
    const u64* wblk = s_W + to * WBLK;

    u64 acc[32];
#pragma unroll
    for (int i = 0; i < 32; i++) acc[i] = 0ull;

#pragma unroll 4
    for (int kk = 0; kk < 16; kk++) {
        const int z = kk & 7;
        u64 A0[4], A1[4];
#pragma unroll
        for (int i2 = 0; i2 < 4; i2++) {
            const ulonglong2 av = A2[kk * 128 + ((ti + 32 * i2) ^ z)];
            A0[i2] = av.x; A1[i2] = av.y;
        }
        u64 W0[8], W1[8];
        const ulonglong2* wp0 = (const ulonglong2*)(wblk + (2 * kk) * 8);
        const ulonglong2* wp1 = (const ulonglong2*)(wblk + (2 * kk + 1) * 8);
#pragma unroll
        for (int c = 0; c < 4; c++) {
            const ulonglong2 a = wp0[c]; W0[2 * c] = a.x; W0[2 * c + 1] = a.y;
            const ulonglong2 b = wp1[c]; W1[2 * c] = b.x; W1[2 * c + 1] = b.y;
        }
#pragma unroll
        for (int i2 = 0; i2 < 4; i2++)
#pragma unroll
            for (int j = 0; j < 8; j++) {
                FFMA2(acc[i2 * 8 + j], A0[i2], W0[j]);
                FFMA2(acc[i2 * 8 + j], A1[i2], W1[j]);
            }
    }

    // epilogue: coalesced STG (warp covers 4 consecutive item rows per i2)
#pragma unroll
    for (int i2 = 0; i2 < 4; i2++) {
        float r[8];
#pragma unroll
        for (int j = 0; j < 8; j++) {
            float lo, hi;
            UNPACK2(lo, hi, acc[i2 * 8 + j]);
            r[j] = lo + hi + bb[j];
        }
        const int item = blockIdx.x * 128 + ti + 32 * i2;
        float* orow = out + (size_t)item * 64 + to * 8;
        *(float4*)(orow)     = make_float4(r[0], r[1], r[2], r[3]);
        *(float4*)(orow + 4) = make_float4(r[4], r[5], r[6], r[7]);
    }
}

// ---------------------------------------------------------------------------
extern "C" void kernel_launch(void* const* d_in, const int* in_sizes, int n_in,
                              void* d_out, int out_size)
{
    const int*   seqs = (const int*)  d_in[0];
    const int*   qtok = (const int*)  d_in[1];
    const float* emb  = (const float*)d_in[2];
    const float* sw1  = (const float*)d_in[3];
    const float* sb1  = (const float*)d_in[4];
    const float* sw2  = (const float*)d_in[5];
    const float* sb2  = (const float*)d_in[6];
    const float* w1   = (const float*)d_in[7];
    const float* b1   = (const float*)d_in[8];
    const float* w2   = (const float*)d_in[9];
    const float* b2   = (const float*)d_in[10];
    float* out = (float*)d_out;

    cudaFuncSetAttribute(main_k, cudaFuncAttributeMaxDynamicSharedMemorySize, SMEM_TOTAL);

    precompute_k<<<64, 128>>>(emb, sw1, sb1, sw2, sb2, w1, b1);
    main_k<<<NB / 128, 256, SMEM_TOTAL>>>(seqs, qtok, w2, b2, out);
}